// round 5
// baseline (speedup 1.0000x reference)
#include <cuda_runtime.h>

// Problem constants (fixed by reference setup_inputs)
#define Hh     32
#define EPB    4          // batch elements per block
#define TIN    999        // teacher-forced steps
#define STEPS  1999       // TIN + future(1000)
#define BATCH  1024

typedef unsigned long long u64;

// Packed 2xfp32 FMA (sm_103a FFMA2)
__device__ __forceinline__ u64 fma2(u64 a, u64 b, u64 c) {
    u64 d;
    asm("fma.rn.f32x2 %0, %1, %2, %3;" : "=l"(d) : "l"(a), "l"(b), "l"(c));
    return d;
}
__device__ __forceinline__ float f2lo(u64 a) { return __uint_as_float((unsigned)a); }
__device__ __forceinline__ float f2hi(u64 a) { return __uint_as_float((unsigned)(a >> 32)); }

__device__ __forceinline__ float ex2a(float x) { float y; asm("ex2.approx.f32 %0, %1;" : "=f"(y) : "f"(x)); return y; }
__device__ __forceinline__ float rcpa(float x) { float y; asm("rcp.approx.f32 %0, %1;" : "=f"(y) : "f"(x)); return y; }

// tanh(x) = 1 - 2/(1 + 2^(2x*log2e)); ~1e-7 accurate
__device__ __forceinline__ float tanh_(float x) {
    return fmaf(-2.0f, rcpa(1.0f + ex2a(2.8853900817779268f * x)), 1.0f);
}

__global__ __launch_bounds__(128, 2) void lstm_seq_kernel(
    const float* __restrict__ input,                                   // [B, TIN]
    const float* __restrict__ W_ih1, const float* __restrict__ W_hh1,  // [4H,1], [4H,H]
    const float* __restrict__ b_ih1, const float* __restrict__ b_hh1,  // [4H]
    const float* __restrict__ W_ih2, const float* __restrict__ W_hh2,  // [4H,H], [4H,H]
    const float* __restrict__ b_ih2, const float* __restrict__ b_hh2,  // [4H]
    const float* __restrict__ W_lin, const float* __restrict__ b_lin,  // [1,H], [1]
    float* __restrict__ out)                                           // [B, STEPS]
{
    __shared__ float sh_in[EPB][TIN];                       // staged input rows (~16KB)
    __shared__ __align__(16) float sh_h1[2][EPB][Hh];       // double-buffered hidden states
    __shared__ __align__(16) float sh_h2[2][EPB][Hh];
    __shared__ __align__(16) float sh_p[EPB][4];            // per-warp head partials

    const int tid  = threadIdx.x;
    const int w    = tid >> 5;          // warp id 0..3
    const int l    = tid & 31;          // lane
    const int g    = l >> 3;            // gate index 0..3 (i,f,g,o)
    const int base = l & 7;             // unit-subindex within warp
    const int j    = base * 4 + w;      // hidden unit 0..31 owned (4-lane redundant)
    const int r    = g * 32 + j;        // gate row 0..127 this thread computes
    const int b0   = blockIdx.x * EPB;

    // Unified activation constants: sigm for g in {0,1,3}, tanh for g==2
    const float ak = (g == 2) ?  2.8853900817779268f : -1.4426950408889634f;
    const float as = (g == 2) ? -2.0f : 1.0f;
    const float ad = (g == 2) ?  1.0f : 0.0f;

    // ---- Weights into registers (packed pairs along k) ----
    const float wih1 = W_ih1[r];
    const float bb1  = b_ih1[r] + b_hh1[r];
    const float bb2  = b_ih2[r] + b_hh2[r];
    const float wlin = W_lin[j];
    const float blin = b_lin[0];

    u64 whh1p[Hh / 2], wih2p[Hh / 2], whh2p[Hh / 2];
    {
        const u64* p1 = (const u64*)(W_hh1 + r * Hh);   // rows 128B -> 8B aligned
        const u64* p2 = (const u64*)(W_ih2 + r * Hh);
        const u64* p3 = (const u64*)(W_hh2 + r * Hh);
#pragma unroll
        for (int i = 0; i < Hh / 2; i++) { whh1p[i] = p1[i]; wih2p[i] = p2[i]; whh2p[i] = p3[i]; }
    }

    // ---- Stage input rows into SMEM ----
#pragma unroll
    for (int e = 0; e < EPB; e++)
        for (int t = tid; t < TIN; t += 128)
            sh_in[e][t] = input[(b0 + e) * TIN + t];

    // ---- Zero initial hidden state (parity-0 buffers) ----
    sh_h1[0][w][l] = 0.0f;
    sh_h2[0][w][l] = 0.0f;

    float c1[EPB], c2[EPB], xfb[EPB];
#pragma unroll
    for (int e = 0; e < EPB; e++) { c1[e] = 0.0f; c2[e] = 0.0f; xfb[e] = 0.0f; }
    __syncthreads();

#pragma unroll 1
    for (int t = 0; t < STEPS; t++) {
        const int p = t & 1;

        // ======== Layer 1: gates + in-warp combine (no barrier, no sh_z) ========
#pragma unroll
        for (int e = 0; e < EPB; e++) {
            float x = (t < TIN) ? sh_in[e][t] : xfb[e];
            const ulonglong2* hp = (const ulonglong2*)sh_h1[p][e];   // broadcast LDS.128
            u64 a0 = 0ull, a1 = 0ull;
#pragma unroll
            for (int i = 0; i < 8; i++) {
                ulonglong2 hv = hp[i];
                a0 = fma2(whh1p[2 * i],     hv.x, a0);
                a1 = fma2(whh1p[2 * i + 1], hv.y, a1);
            }
            float z = fmaf(wih1, x, bb1)
                    + ((f2lo(a0) + f2hi(a0)) + (f2lo(a1) + f2hi(a1)));
            // activate own gate, then gather all 4 activated gates of unit j
            float a  = fmaf(as, rcpa(1.0f + ex2a(ak * z)), ad);
            float ai = __shfl_sync(0xffffffffu, a, base);
            float af = __shfl_sync(0xffffffffu, a, base + 8);
            float ag = __shfl_sync(0xffffffffu, a, base + 16);
            float ao = __shfl_sync(0xffffffffu, a, base + 24);
            float cn = fmaf(af, c1[e], ai * ag);
            c1[e] = cn;
            float hn = ao * tanh_(cn);
            if (g == 0) sh_h1[p ^ 1][e][j] = hn;      // conflict-free STS (8 lanes)
        }
        __syncthreads();   // B1: h1_new visible to all warps

        // ======== Layer 2: gates + combine + linear-head partials ========
#pragma unroll
        for (int e = 0; e < EPB; e++) {
            const ulonglong2* h1p = (const ulonglong2*)sh_h1[p ^ 1][e];
            const ulonglong2* h2p = (const ulonglong2*)sh_h2[p][e];
            u64 a0 = 0ull, a1 = 0ull, a2 = 0ull, a3 = 0ull;
#pragma unroll
            for (int i = 0; i < 8; i++) {
                ulonglong2 hv1 = h1p[i];
                ulonglong2 hv2 = h2p[i];
                a0 = fma2(wih2p[2 * i],     hv1.x, a0);
                a1 = fma2(wih2p[2 * i + 1], hv1.y, a1);
                a2 = fma2(whh2p[2 * i],     hv2.x, a2);
                a3 = fma2(whh2p[2 * i + 1], hv2.y, a3);
            }
            float z = bb2 + ((f2lo(a0) + f2hi(a0)) + (f2lo(a1) + f2hi(a1)))
                          + ((f2lo(a2) + f2hi(a2)) + (f2lo(a3) + f2hi(a3)));
            float a  = fmaf(as, rcpa(1.0f + ex2a(ak * z)), ad);
            float ai = __shfl_sync(0xffffffffu, a, base);
            float af = __shfl_sync(0xffffffffu, a, base + 8);
            float ag = __shfl_sync(0xffffffffu, a, base + 16);
            float ao = __shfl_sync(0xffffffffu, a, base + 24);
            float cn = fmaf(af, c2[e], ai * ag);
            c2[e] = cn;
            float hn = ao * tanh_(cn);
            if (g == 0) sh_h2[p ^ 1][e][j] = hn;

            // head partial: lanes 0..7 of each 8-group hold this warp's 8 distinct units
            float pp = wlin * hn;
            pp += __shfl_xor_sync(0xffffffffu, pp, 1);
            pp += __shfl_xor_sync(0xffffffffu, pp, 2);
            pp += __shfl_xor_sync(0xffffffffu, pp, 4);
            if (l == 0) sh_p[e][w] = pp;
        }
        __syncthreads();   // B2: h2_new + partials visible

        // ======== Output + feedback (computed redundantly by all threads) ========
#pragma unroll
        for (int e = 0; e < EPB; e++) {
            float4 pv = *(const float4*)sh_p[e];      // broadcast LDS.128
            xfb[e] = ((pv.x + pv.y) + (pv.z + pv.w)) + blin;
        }
        if (tid < EPB)
            out[(size_t)(b0 + tid) * STEPS + t] = xfb[tid];
    }
}

extern "C" void kernel_launch(void* const* d_in, const int* in_sizes, int n_in,
                              void* d_out, int out_size) {
    const float* input = (const float*)d_in[0];
    const float* W_ih1 = (const float*)d_in[1];
    const float* W_hh1 = (const float*)d_in[2];
    const float* b_ih1 = (const float*)d_in[3];
    const float* b_hh1 = (const float*)d_in[4];
    const float* W_ih2 = (const float*)d_in[5];
    const float* W_hh2 = (const float*)d_in[6];
    const float* b_ih2 = (const float*)d_in[7];
    const float* b_hh2 = (const float*)d_in[8];
    const float* W_lin = (const float*)d_in[9];
    const float* b_lin = (const float*)d_in[10];
    float* out = (float*)d_out;

    lstm_seq_kernel<<<BATCH / EPB, 128>>>(input, W_ih1, W_hh1, b_ih1, b_hh1,
                                          W_ih2, W_hh2, b_ih2, b_hh2,
                                          W_lin, b_lin, out);
}

// round 6
// speedup vs baseline: 1.6457x; 1.6457x over previous
#include <cuda_runtime.h>

// Problem constants (fixed by reference setup_inputs)
#define Hh     32
#define EPB    2          // batch elements per block
#define TIN    999        // teacher-forced steps
#define STEPS  1999       // TIN + future(1000)
#define BATCH  1024

typedef unsigned long long u64;

// Packed 2xfp32 FMA (sm_103a FFMA2)
__device__ __forceinline__ u64 fma2(u64 a, u64 b, u64 c) {
    u64 d;
    asm("fma.rn.f32x2 %0, %1, %2, %3;" : "=l"(d) : "l"(a), "l"(b), "l"(c));
    return d;
}
__device__ __forceinline__ float f2lo(u64 a) { return __uint_as_float((unsigned)a); }
__device__ __forceinline__ float f2hi(u64 a) { return __uint_as_float((unsigned)(a >> 32)); }

__device__ __forceinline__ float ex2a(float x) { float y; asm("ex2.approx.f32 %0, %1;" : "=f"(y) : "f"(x)); return y; }
__device__ __forceinline__ float rcpa(float x) { float y; asm("rcp.approx.f32 %0, %1;" : "=f"(y) : "f"(x)); return y; }

// sigmoid(x) = 1/(1 + 2^(-x*log2e)); ~1e-7 accurate
__device__ __forceinline__ float sigm(float x) {
    return rcpa(1.0f + ex2a(-1.4426950408889634f * x));
}
// tanh(x) = 1 - 2/(1 + 2^(2x*log2e)); ~1e-7 accurate
__device__ __forceinline__ float tanh_(float x) {
    return fmaf(-2.0f, rcpa(1.0f + ex2a(2.8853900817779268f * x)), 1.0f);
}

__global__ __launch_bounds__(128) void lstm_seq_kernel(
    const float* __restrict__ input,                                   // [B, TIN]
    const float* __restrict__ W_ih1, const float* __restrict__ W_hh1,  // [4H,1], [4H,H]
    const float* __restrict__ b_ih1, const float* __restrict__ b_hh1,  // [4H]
    const float* __restrict__ W_ih2, const float* __restrict__ W_hh2,  // [4H,H], [4H,H]
    const float* __restrict__ b_ih2, const float* __restrict__ b_hh2,  // [4H]
    const float* __restrict__ W_lin, const float* __restrict__ b_lin,  // [1,H], [1]
    float* __restrict__ out)                                           // [B, STEPS]
{
    __shared__ float sh_in[EPB][TIN];                       // staged input rows (~8KB)
    __shared__ __align__(16) float sh_h1[EPB][Hh];
    __shared__ __align__(16) float sh_h2[EPB][Hh];
    __shared__ float sh_zA[EPB][4 * Hh];                    // layer-1 pre-activations
    __shared__ float sh_zB[EPB][4 * Hh];                    // layer-2 pre-activations
    __shared__ float sh_x[EPB];                             // fed-back output

    const int r    = threadIdx.x;        // gate row 0..127
    const int lane = r & 31;
    const int b0   = blockIdx.x * EPB;

    // combine-phase ownership: threads 0..63 -> (element ce, unit cj)
    const int ce = r >> 5;               // valid when r < 64  (EPB==2)
    const int cj = lane;

    // ---- Weights into registers (packed pairs along k) ----
    const float wih1 = W_ih1[r];
    const float bb1  = b_ih1[r] + b_hh1[r];
    const float bb2  = b_ih2[r] + b_hh2[r];
    const float wlin = W_lin[lane];
    const float blin = b_lin[0];

    u64 whh1p[Hh / 2], wih2p[Hh / 2], whh2p[Hh / 2];
    {
        const u64* p1 = (const u64*)(W_hh1 + r * Hh);  // rows are 128B -> 8B aligned
        const u64* p2 = (const u64*)(W_ih2 + r * Hh);
        const u64* p3 = (const u64*)(W_hh2 + r * Hh);
#pragma unroll
        for (int i = 0; i < Hh / 2; i++) { whh1p[i] = p1[i]; wih2p[i] = p2[i]; whh2p[i] = p3[i]; }
    }

    // ---- Stage input rows into SMEM ----
#pragma unroll
    for (int e = 0; e < EPB; e++)
        for (int t = r; t < TIN; t += 128)
            sh_in[e][t] = input[(b0 + e) * TIN + t];

    // ---- Zero initial state; c-states live in registers of the combine thread ----
    if (r < EPB * Hh) {
        sh_h1[ce][cj] = 0.0f;
        sh_h2[ce][cj] = 0.0f;
    }
    float c1 = 0.0f, c2 = 0.0f;          // owned by thread (ce, cj), r < 64
    __syncthreads();

    // ================= Teacher-forced phase: 3 barriers/step =================
#pragma unroll 1
    for (int t = 0; t < TIN; t++) {
        // P1: layer-1 gate pre-activations
#pragma unroll
        for (int e = 0; e < EPB; e++) {
            float x = sh_in[e][t];
            const ulonglong2* hp = (const ulonglong2*)sh_h1[e];   // broadcast LDS.128
            u64 a0 = 0ull, a1 = 0ull;
#pragma unroll
            for (int i = 0; i < 8; i++) {
                ulonglong2 hv = hp[i];
                a0 = fma2(whh1p[2 * i],     hv.x, a0);
                a1 = fma2(whh1p[2 * i + 1], hv.y, a1);
            }
            sh_zA[e][r] = fmaf(wih1, x, bb1)
                        + ((f2lo(a0) + f2hi(a0)) + (f2lo(a1) + f2hi(a1)));
        }
        __syncthreads();

        // P2: layer-1 combine (threads 0..63)
        if (r < EPB * Hh) {
            float zi = sh_zA[ce][cj],          zf = sh_zA[ce][Hh + cj];
            float zg = sh_zA[ce][2 * Hh + cj], zo = sh_zA[ce][3 * Hh + cj];
            float cn = fmaf(sigm(zf), c1, sigm(zi) * tanh_(zg));
            c1 = cn;
            sh_h1[ce][cj] = sigm(zo) * tanh_(cn);
        }
        __syncthreads();

        // P3: layer-2 gate pre-activations
#pragma unroll
        for (int e = 0; e < EPB; e++) {
            const ulonglong2* h1p = (const ulonglong2*)sh_h1[e];
            const ulonglong2* h2p = (const ulonglong2*)sh_h2[e];
            u64 a0 = 0ull, a1 = 0ull, a2 = 0ull, a3 = 0ull;
#pragma unroll
            for (int i = 0; i < 8; i++) {
                ulonglong2 hv1 = h1p[i];
                ulonglong2 hv2 = h2p[i];
                a0 = fma2(wih2p[2 * i],     hv1.x, a0);
                a1 = fma2(wih2p[2 * i + 1], hv1.y, a1);
                a2 = fma2(whh2p[2 * i],     hv2.x, a2);
                a3 = fma2(whh2p[2 * i + 1], hv2.y, a3);
            }
            sh_zB[e][r] = bb2 + ((f2lo(a0) + f2hi(a0)) + (f2lo(a1) + f2hi(a1)))
                              + ((f2lo(a2) + f2hi(a2)) + (f2lo(a3) + f2hi(a3)));
        }
        __syncthreads();

        // P4: layer-2 combine + head (threads 0..63; warps 2-3 flow into next P1)
        // No barrier: P4 touches sh_zB/sh_h2/out only; next P1 touches sh_zA/sh_h1/sh_in.
        if (r < EPB * Hh) {
            float zi = sh_zB[ce][cj],          zf = sh_zB[ce][Hh + cj];
            float zg = sh_zB[ce][2 * Hh + cj], zo = sh_zB[ce][3 * Hh + cj];
            float cn = fmaf(sigm(zf), c2, sigm(zi) * tanh_(zg));
            c2 = cn;
            float hn = sigm(zo) * tanh_(cn);
            sh_h2[ce][cj] = hn;

            float p = wlin * hn;                 // head: full-warp reduce (warps 0,1)
#pragma unroll
            for (int off = 16; off; off >>= 1)
                p += __shfl_xor_sync(0xffffffffu, p, off);
            if (cj == 0) {
                float o = p + blin;
                sh_x[ce] = o;                    // consumed by gen phase (barrier below)
                out[(size_t)(b0 + ce) * STEPS + t] = o;
            }
        }
    }

    // ================= Autoregressive phase: 4 barriers/step =================
#pragma unroll 1
    for (int t = TIN; t < STEPS; t++) {
        __syncthreads();                         // protect sh_x/sh_h2 from prior P4

        // P1: layer-1 gates with fed-back x
#pragma unroll
        for (int e = 0; e < EPB; e++) {
            float x = sh_x[e];
            const ulonglong2* hp = (const ulonglong2*)sh_h1[e];
            u64 a0 = 0ull, a1 = 0ull;
#pragma unroll
            for (int i = 0; i < 8; i++) {
                ulonglong2 hv = hp[i];
                a0 = fma2(whh1p[2 * i],     hv.x, a0);
                a1 = fma2(whh1p[2 * i + 1], hv.y, a1);
            }
            sh_zA[e][r] = fmaf(wih1, x, bb1)
                        + ((f2lo(a0) + f2hi(a0)) + (f2lo(a1) + f2hi(a1)));
        }
        __syncthreads();

        if (r < EPB * Hh) {
            float zi = sh_zA[ce][cj],          zf = sh_zA[ce][Hh + cj];
            float zg = sh_zA[ce][2 * Hh + cj], zo = sh_zA[ce][3 * Hh + cj];
            float cn = fmaf(sigm(zf), c1, sigm(zi) * tanh_(zg));
            c1 = cn;
            sh_h1[ce][cj] = sigm(zo) * tanh_(cn);
        }
        __syncthreads();

#pragma unroll
        for (int e = 0; e < EPB; e++) {
            const ulonglong2* h1p = (const ulonglong2*)sh_h1[e];
            const ulonglong2* h2p = (const ulonglong2*)sh_h2[e];
            u64 a0 = 0ull, a1 = 0ull, a2 = 0ull, a3 = 0ull;
#pragma unroll
            for (int i = 0; i < 8; i++) {
                ulonglong2 hv1 = h1p[i];
                ulonglong2 hv2 = h2p[i];
                a0 = fma2(wih2p[2 * i],     hv1.x, a0);
                a1 = fma2(wih2p[2 * i + 1], hv1.y, a1);
                a2 = fma2(whh2p[2 * i],     hv2.x, a2);
                a3 = fma2(whh2p[2 * i + 1], hv2.y, a3);
            }
            sh_zB[e][r] = bb2 + ((f2lo(a0) + f2hi(a0)) + (f2lo(a1) + f2hi(a1)))
                              + ((f2lo(a2) + f2hi(a2)) + (f2lo(a3) + f2hi(a3)));
        }
        __syncthreads();

        if (r < EPB * Hh) {
            float zi = sh_zB[ce][cj],          zf = sh_zB[ce][Hh + cj];
            float zg = sh_zB[ce][2 * Hh + cj], zo = sh_zB[ce][3 * Hh + cj];
            float cn = fmaf(sigm(zf), c2, sigm(zi) * tanh_(zg));
            c2 = cn;
            float hn = sigm(zo) * tanh_(cn);
            sh_h2[ce][cj] = hn;

            float p = wlin * hn;
#pragma unroll
            for (int off = 16; off; off >>= 1)
                p += __shfl_xor_sync(0xffffffffu, p, off);
            if (cj == 0) {
                float o = p + blin;
                sh_x[ce] = o;
                out[(size_t)(b0 + ce) * STEPS + t] = o;
            }
        }
    }
}

extern "C" void kernel_launch(void* const* d_in, const int* in_sizes, int n_in,
                              void* d_out, int out_size) {
    const float* input = (const float*)d_in[0];
    const float* W_ih1 = (const float*)d_in[1];
    const float* W_hh1 = (const float*)d_in[2];
    const float* b_ih1 = (const float*)d_in[3];
    const float* b_hh1 = (const float*)d_in[4];
    const float* W_ih2 = (const float*)d_in[5];
    const float* W_hh2 = (const float*)d_in[6];
    const float* b_ih2 = (const float*)d_in[7];
    const float* b_hh2 = (const float*)d_in[8];
    const float* W_lin = (const float*)d_in[9];
    const float* b_lin = (const float*)d_in[10];
    float* out = (float*)d_out;

    lstm_seq_kernel<<<BATCH / EPB, 128>>>(input, W_ih1, W_hh1, b_ih1, b_hh1,
                                          W_ih2, W_hh2, b_ih2, b_hh2,
                                          W_lin, b_lin, out);
}